// round 3
// baseline (speedup 1.0000x reference)
#include <cuda_runtime.h>
#include <cuda_bf16.h>

// ---------------------------------------------------------------------------
// GCN layer: h = dropout(relu( segsum_dst( (feat*rsqrt(deg_out))[src] ) @ W
//                              * rsqrt(deg_in) + b ))
// ---------------------------------------------------------------------------

#define N_NODES   50000
#define D_FEAT    256
#define N_TOTAL   (N_NODES * D_FEAT)          // 12,800,000
#define N_WORDS   (N_TOTAL / 32)              // 400,000 mask words

__device__ float        g_agg[N_TOTAL];       // 51.2 MB aggregation buffer
__device__ float        g_rs_out[N_NODES];
__device__ float        g_rs_in[N_NODES];
__device__ int          g_deg_out[N_NODES];
__device__ int          g_deg_in[N_NODES];
__device__ unsigned int g_mask[N_WORDS];

// ---------------------------------------------------------------------------
// threefry2x32 (JAX PRNG), key = (0, 42), partitionable layout
// ---------------------------------------------------------------------------
__device__ __forceinline__ unsigned int rotl32(unsigned int x, int r) {
    return (x << r) | (x >> (32 - r));
}

__device__ __forceinline__ void threefry2x32(unsigned int k0, unsigned int k1,
                                             unsigned int x0, unsigned int x1,
                                             unsigned int& o0, unsigned int& o1) {
    unsigned int ks2 = k0 ^ k1 ^ 0x1BD11BDAu;
    x0 += k0; x1 += k1;
#define TF_RND(r) { x0 += x1; x1 = rotl32(x1, r); x1 ^= x0; }
    TF_RND(13) TF_RND(15) TF_RND(26) TF_RND(6)
    x0 += k1;  x1 += ks2 + 1u;
    TF_RND(17) TF_RND(29) TF_RND(16) TF_RND(24)
    x0 += ks2; x1 += k0 + 2u;
    TF_RND(13) TF_RND(15) TF_RND(26) TF_RND(6)
    x0 += k0;  x1 += k1 + 3u;
    TF_RND(17) TF_RND(29) TF_RND(16) TF_RND(24)
    x0 += k1;  x1 += ks2 + 4u;
    TF_RND(13) TF_RND(15) TF_RND(26) TF_RND(6)
    x0 += ks2; x1 += k0 + 5u;
#undef TF_RND
    o0 = x0; o1 = x1;
}

__device__ __forceinline__ bool keep_from_bits(unsigned int bits) {
    float f = __uint_as_float((bits >> 9) | 0x3f800000u) - 1.0f;
    return f < 0.9f;
}

// ---------------------------------------------------------------------------
// Zero kernels (split so deg-zero can run on the degree stream)
// ---------------------------------------------------------------------------
__global__ void k_zero_agg() {
    int i = blockIdx.x * blockDim.x + threadIdx.x;
    if (i < N_TOTAL / 4)
        ((float4*)g_agg)[i] = make_float4(0.f, 0.f, 0.f, 0.f);
}

__global__ void k_zero_deg() {
    int i = blockIdx.x * blockDim.x + threadIdx.x;
    if (i < N_NODES) {
        g_deg_out[i] = 0;
        g_deg_in[i]  = 0;
    }
}

__global__ void k_degrees(const int* __restrict__ src, const int* __restrict__ dst, int nE) {
    int e = blockIdx.x * blockDim.x + threadIdx.x;
    if (e < nE) {
        atomicAdd(&g_deg_out[src[e]], 1);
        atomicAdd(&g_deg_in[dst[e]], 1);
    }
}

__global__ void k_rsqrt(int nN) {
    int i = blockIdx.x * blockDim.x + threadIdx.x;
    if (i < nN) {
        int dout = g_deg_out[i]; if (dout < 1) dout = 1;
        int din  = g_deg_in[i];  if (din  < 1) din  = 1;
        g_rs_out[i] = rsqrtf((float)dout);
        g_rs_in[i]  = rsqrtf((float)din);
    }
}

// ---------------------------------------------------------------------------
// Edge scatter-aggregate (one warp per edge, vector reductions)
// ---------------------------------------------------------------------------
__global__ void k_scatter(const float* __restrict__ feat,
                          const int* __restrict__ src,
                          const int* __restrict__ dst, int nE) {
    int warp = (blockIdx.x * blockDim.x + threadIdx.x) >> 5;
    int lane = threadIdx.x & 31;
    if (warp >= nE) return;
    int s = src[warp];
    int d = dst[warp];
    float rs = g_rs_out[s];
    const float4* fr = (const float4*)(feat + (size_t)s * D_FEAT);
    float4* ar = (float4*)(g_agg + (size_t)d * D_FEAT);
#pragma unroll
    for (int u = 0; u < 2; u++) {
        int idx = lane + u * 32;
        float4 v = fr[idx];
        v.x *= rs; v.y *= rs; v.z *= rs; v.w *= rs;
        asm volatile("red.global.add.v4.f32 [%0], {%1,%2,%3,%4};"
                     :: "l"(ar + idx), "f"(v.x), "f"(v.y), "f"(v.z), "f"(v.w)
                     : "memory");
    }
}

// ---------------------------------------------------------------------------
// Dropout bitmask — JAX threefry_partitionable: counter (0, idx), XOR combiner
// ---------------------------------------------------------------------------
__global__ void k_mask() {
    int t = blockIdx.x * blockDim.x + threadIdx.x;
    if (t >= N_WORDS) return;
    unsigned int base = (unsigned int)t * 32u;
    unsigned int w = 0u;
#pragma unroll 4
    for (int i = 0; i < 32; i++) {
        unsigned int o0, o1;
        threefry2x32(0u, 42u, 0u, base + i, o0, o1);
        w |= (unsigned int)keep_from_bits(o0 ^ o1) << i;
    }
    g_mask[t] = w;
}

// ---------------------------------------------------------------------------
// GEMM (agg @ W) + fused epilogue. 64x256 tile => A streamed exactly once.
// BK=16, 256 threads, 8x8 per thread, packed f32x2 FMA.
// ---------------------------------------------------------------------------
#define BM 64
#define BN 256
#define BK 16
#define TM 8
#define TN 8

__device__ __forceinline__ unsigned long long pack2(float x, float y) {
    unsigned long long r;
    asm("mov.b64 %0, {%1, %2};" : "=l"(r) : "f"(x), "f"(y));
    return r;
}

__device__ __forceinline__ void ffma2(unsigned long long& d,
                                      unsigned long long a, unsigned long long b) {
    asm("fma.rn.f32x2 %0, %1, %2, %0;" : "+l"(d) : "l"(a), "l"(b));
}

__global__ __launch_bounds__(256, 2)
void k_gemm_epilogue(const float* __restrict__ Wm,
                     const float* __restrict__ bvec,
                     float* __restrict__ out, int M) {
    __shared__ float As[BK][BM + 4];
    __shared__ float Ws[BK][BN];

    int tid = threadIdx.x;
    int tx = tid & 31;          // 0..31 -> column group (8 cols each, covers 256)
    int ty = tid >> 5;          // 0..7  -> row group (8 rows each, covers 64)
    int bm = blockIdx.x * BM;

    unsigned long long acc[TM][TN / 2];
#pragma unroll
    for (int i = 0; i < TM; i++)
#pragma unroll
        for (int p = 0; p < TN / 2; p++) acc[i][p] = 0ull;

    const float* A = g_agg;

    for (int k0 = 0; k0 < D_FEAT; k0 += BK) {
        // A tile: 64 rows x 16 k = 256 float4, 1 per thread, stored transposed
        {
            int r = tid >> 2;                 // 0..63
            int c = (tid & 3) << 2;           // 0,4,8,12
            int grow = bm + r;
            float4 v;
            if (grow < M)
                v = *(const float4*)(A + (size_t)grow * D_FEAT + k0 + c);
            else
                v = make_float4(0.f, 0.f, 0.f, 0.f);
            As[c + 0][r] = v.x;
            As[c + 1][r] = v.y;
            As[c + 2][r] = v.z;
            As[c + 3][r] = v.w;
        }
        // W tile: 16 k x 256 cols = 1024 float4, 4 per thread
#pragma unroll
        for (int u = 0; u < 4; u++) {
            int f = tid + u * 256;
            int r = f >> 6;                   // 0..15
            int c = (f & 63) << 2;            // 0..252
            *(float4*)&Ws[r][c] = *(const float4*)(Wm + (size_t)(k0 + r) * D_FEAT + c);
        }
        __syncthreads();

#pragma unroll
        for (int k = 0; k < BK; k++) {
            unsigned long long ap[TM];
#pragma unroll
            for (int i = 0; i < TM; i++) {
                float a = As[k][ty * TM + i];
                ap[i] = pack2(a, a);
            }
            union { float4 f4[2]; unsigned long long u[4]; } wv;
            wv.f4[0] = *(float4*)&Ws[k][tx * TN];
            wv.f4[1] = *(float4*)&Ws[k][tx * TN + 4];
#pragma unroll
            for (int i = 0; i < TM; i++)
#pragma unroll
                for (int p = 0; p < TN / 2; p++)
                    ffma2(acc[i][p], ap[i], wv.u[p]);
        }
        __syncthreads();
    }

    // Epilogue: * rs_in + b, relu, dropout, store
    int colBase = tx * TN;
    float bias[TN];
    {
        float4 b0 = *(const float4*)(bvec + colBase);
        float4 b1 = *(const float4*)(bvec + colBase + 4);
        bias[0] = b0.x; bias[1] = b0.y; bias[2] = b0.z; bias[3] = b0.w;
        bias[4] = b1.x; bias[5] = b1.y; bias[6] = b1.z; bias[7] = b1.w;
    }
    const float inv_keep = 1.0f / 0.9f;
#pragma unroll
    for (int i = 0; i < TM; i++) {
        int row = bm + ty * TM + i;
        if (row < M) {
            float rs = g_rs_in[row];
            union { unsigned long long u[4]; float f[8]; float4 q[2]; } r;
#pragma unroll
            for (int p = 0; p < TN / 2; p++) r.u[p] = acc[i][p];
            unsigned int flat0 = (unsigned int)row * D_FEAT + colBase;
            unsigned int mword = g_mask[flat0 >> 5];
            int sh = flat0 & 31;
#pragma unroll
            for (int j = 0; j < TN; j++) {
                float v = r.f[j] * rs + bias[j];
                v = fmaxf(v, 0.0f);
                v = ((mword >> (sh + j)) & 1u) ? v * inv_keep : 0.0f;
                r.f[j] = v;
            }
            *(float4*)(out + flat0)     = r.q[0];
            *(float4*)(out + flat0 + 4) = r.q[1];
        }
    }
}

// ---------------------------------------------------------------------------
// Launch: fork/join streams inside graph capture.
//   main (0): zero_agg ............ scatter ........ gemm
//   s1      : zero_deg, degrees, rsqrt --e1--> (scatter dep)
//   s2      : mask -------------------e2--> (gemm dep)
// ---------------------------------------------------------------------------
extern "C" void kernel_launch(void* const* d_in, const int* in_sizes, int n_in,
                              void* d_out, int out_size) {
    const float* feat = (const float*)d_in[0];
    const float* Wm   = (const float*)d_in[1];
    const float* bvec = (const float*)d_in[2];
    const int*   src  = (const int*)d_in[3];
    const int*   dst  = (const int*)d_in[4];
    float* out = (float*)d_out;

    int M  = in_sizes[0] / D_FEAT;   // 50000
    int nE = in_sizes[3];            // 400000

    static cudaStream_t s1 = nullptr, s2 = nullptr;
    static cudaEvent_t e0 = nullptr, e1 = nullptr, e2 = nullptr;
    if (!s1) {
        cudaStreamCreateWithFlags(&s1, cudaStreamNonBlocking);
        cudaStreamCreateWithFlags(&s2, cudaStreamNonBlocking);
        cudaEventCreateWithFlags(&e0, cudaEventDisableTiming);
        cudaEventCreateWithFlags(&e1, cudaEventDisableTiming);
        cudaEventCreateWithFlags(&e2, cudaEventDisableTiming);
    }

    // Fork from the captured (legacy default) stream
    cudaEventRecord(e0, 0);
    cudaStreamWaitEvent(s1, e0, 0);
    cudaStreamWaitEvent(s2, e0, 0);

    // Branch s1: degree pipeline
    k_zero_deg<<<(N_NODES + 255) / 256, 256, 0, s1>>>();
    k_degrees<<<(nE + 255) / 256, 256, 0, s1>>>(src, dst, nE);
    k_rsqrt<<<(M + 255) / 256, 256, 0, s1>>>(M);
    cudaEventRecord(e1, s1);

    // Branch s2: dropout mask (pure ALU, hides under memory work)
    k_mask<<<(N_WORDS + 127) / 128, 128, 0, s2>>>();
    cudaEventRecord(e2, s2);

    // Main: zero the big agg buffer, then scatter (needs e1), then gemm (needs e2)
    k_zero_agg<<<(N_TOTAL / 4 + 255) / 256, 256>>>();
    cudaStreamWaitEvent(0, e1, 0);
    k_scatter<<<(nE + 7) / 8, 256>>>(feat, src, dst, nE);
    cudaStreamWaitEvent(0, e2, 0);
    dim3 grid((M + BM - 1) / BM, 1);
    k_gemm_epilogue<<<grid, 256>>>(Wm, bvec, out, M);
}

// round 4
// speedup vs baseline: 1.4595x; 1.4595x over previous
#include <cuda_runtime.h>
#include <cuda_bf16.h>

// ---------------------------------------------------------------------------
// GCN layer: h = dropout(relu( segsum_dst( (feat*rsqrt(deg_out))[src] ) @ W
//                              * rsqrt(deg_in) + b ))
// ---------------------------------------------------------------------------

#define N_NODES   50000
#define D_FEAT    256
#define N_TOTAL   (N_NODES * D_FEAT)          // 12,800,000

__device__ float g_agg[N_TOTAL];              // 51.2 MB aggregation buffer
__device__ float g_rs_out[N_NODES];
__device__ float g_rs_in[N_NODES];
__device__ int   g_deg_out[N_NODES];
__device__ int   g_deg_in[N_NODES];

// ---------------------------------------------------------------------------
// threefry2x32 (JAX PRNG), key = (0, 42), partitionable layout:
// counter (0, flat_idx), bits = o0 ^ o1, keep = u(bits) < 0.9
// ---------------------------------------------------------------------------
__device__ __forceinline__ unsigned int rotl32(unsigned int x, int r) {
    return (x << r) | (x >> (32 - r));
}

__device__ __forceinline__ void threefry2x32(unsigned int k0, unsigned int k1,
                                             unsigned int x0, unsigned int x1,
                                             unsigned int& o0, unsigned int& o1) {
    unsigned int ks2 = k0 ^ k1 ^ 0x1BD11BDAu;
    x0 += k0; x1 += k1;
#define TF_RND(r) { x0 += x1; x1 = rotl32(x1, r); x1 ^= x0; }
    TF_RND(13) TF_RND(15) TF_RND(26) TF_RND(6)
    x0 += k1;  x1 += ks2 + 1u;
    TF_RND(17) TF_RND(29) TF_RND(16) TF_RND(24)
    x0 += ks2; x1 += k0 + 2u;
    TF_RND(13) TF_RND(15) TF_RND(26) TF_RND(6)
    x0 += k0;  x1 += k1 + 3u;
    TF_RND(17) TF_RND(29) TF_RND(16) TF_RND(24)
    x0 += k1;  x1 += ks2 + 4u;
    TF_RND(13) TF_RND(15) TF_RND(26) TF_RND(6)
    x0 += ks2; x1 += k0 + 5u;
#undef TF_RND
    o0 = x0; o1 = x1;
}

__device__ __forceinline__ float dropout_apply(float v, unsigned int flat) {
    unsigned int o0, o1;
    threefry2x32(0u, 42u, 0u, flat, o0, o1);
    unsigned int bits = o0 ^ o1;
    float u = __uint_as_float((bits >> 9) | 0x3f800000u) - 1.0f;
    return (u < 0.9f) ? v * (1.0f / 0.9f) : 0.0f;
}

// ---------------------------------------------------------------------------
// Setup kernels
// ---------------------------------------------------------------------------
__global__ void k_zero_agg() {
    int i = blockIdx.x * blockDim.x + threadIdx.x;
    if (i < N_TOTAL / 4)
        ((float4*)g_agg)[i] = make_float4(0.f, 0.f, 0.f, 0.f);
}

__global__ void k_zero_deg() {
    int i = blockIdx.x * blockDim.x + threadIdx.x;
    if (i < N_NODES) {
        g_deg_out[i] = 0;
        g_deg_in[i]  = 0;
    }
}

__global__ void k_degrees(const int* __restrict__ src, const int* __restrict__ dst, int nE) {
    int e = blockIdx.x * blockDim.x + threadIdx.x;
    if (e < nE) {
        atomicAdd(&g_deg_out[src[e]], 1);
        atomicAdd(&g_deg_in[dst[e]], 1);
    }
}

__global__ void k_rsqrt(int nN) {
    int i = blockIdx.x * blockDim.x + threadIdx.x;
    if (i < nN) {
        int dout = g_deg_out[i]; if (dout < 1) dout = 1;
        int din  = g_deg_in[i];  if (din  < 1) din  = 1;
        g_rs_out[i] = rsqrtf((float)dout);
        g_rs_in[i]  = rsqrtf((float)din);
    }
}

// ---------------------------------------------------------------------------
// Edge scatter-aggregate (one warp per edge, vector reductions)
// ---------------------------------------------------------------------------
__global__ void k_scatter(const float* __restrict__ feat,
                          const int* __restrict__ src,
                          const int* __restrict__ dst, int nE) {
    int warp = (blockIdx.x * blockDim.x + threadIdx.x) >> 5;
    int lane = threadIdx.x & 31;
    if (warp >= nE) return;
    int s = src[warp];
    int d = dst[warp];
    float rs = g_rs_out[s];
    const float4* fr = (const float4*)(feat + (size_t)s * D_FEAT);
    float4* ar = (float4*)(g_agg + (size_t)d * D_FEAT);
#pragma unroll
    for (int u = 0; u < 2; u++) {
        int idx = lane + u * 32;
        float4 v = fr[idx];
        v.x *= rs; v.y *= rs; v.z *= rs; v.w *= rs;
        asm volatile("red.global.add.v4.f32 [%0], {%1,%2,%3,%4};"
                     :: "l"(ar + idx), "f"(v.x), "f"(v.y), "f"(v.z), "f"(v.w)
                     : "memory");
    }
}

// ---------------------------------------------------------------------------
// tf32 tensor-core GEMM (agg @ W) + fused epilogue (rs_in, bias, relu,
// threefry dropout). BM=128, BN=128, BK=32, 256 threads = 8 warps (4M x 2N),
// warp tile 32x64, mma.m16n8k8.
// ---------------------------------------------------------------------------
#define GBM 128
#define GBN 128
#define GBK 32
#define SLDA 136   // padded smem leading dim (conflict-free: 136 % 32 == 8)

__device__ __forceinline__ unsigned int f2tf32(float f) {
    unsigned int u;
    asm("cvt.rna.tf32.f32 %0, %1;" : "=r"(u) : "f"(f));
    return u;
}

__global__ __launch_bounds__(256, 2)
void k_gemm_epilogue(const float* __restrict__ Wm,
                     const float* __restrict__ bvec,
                     float* __restrict__ out, int M) {
    __shared__ unsigned int As[GBK][SLDA];   // As[k][m], tf32
    __shared__ unsigned int Bs[GBK][SLDA];   // Bs[k][n], tf32

    int tid  = threadIdx.x;
    int lane = tid & 31;
    int wid  = tid >> 5;
    int wm   = wid & 3;          // warp row (4)
    int wn   = wid >> 2;         // warp col (2)
    int g    = lane >> 2;        // group id 0..7
    int q    = lane & 3;         // 0..3

    int bm = blockIdx.x * GBM;
    int bn = blockIdx.y * GBN;

    float c[2][8][4];
#pragma unroll
    for (int i = 0; i < 2; i++)
#pragma unroll
        for (int j = 0; j < 8; j++)
#pragma unroll
            for (int r = 0; r < 4; r++) c[i][j][r] = 0.0f;

    const float* A = g_agg;

    for (int k0 = 0; k0 < D_FEAT; k0 += GBK) {
        // A tile: 128 rows x 32 k -> As[k][m] (transposed), 4 float4/thread
#pragma unroll
        for (int u = 0; u < 4; u++) {
            int f  = tid + u * 256;          // 0..1023
            int r  = f >> 3;                 // row 0..127
            int c4 = (f & 7) << 2;           // k offset 0,4,...,28
            int grow = bm + r;
            float4 v;
            if (grow < M)
                v = *(const float4*)(A + (size_t)grow * D_FEAT + k0 + c4);
            else
                v = make_float4(0.f, 0.f, 0.f, 0.f);
            As[c4 + 0][r] = f2tf32(v.x);
            As[c4 + 1][r] = f2tf32(v.y);
            As[c4 + 2][r] = f2tf32(v.z);
            As[c4 + 3][r] = f2tf32(v.w);
        }
        // B tile: 32 k x 128 n -> Bs[k][n], 4 float4/thread
#pragma unroll
        for (int u = 0; u < 4; u++) {
            int f  = tid + u * 256;
            int r  = f >> 5;                 // k 0..31
            int c4 = (f & 31) << 2;          // n 0..124
            float4 v = *(const float4*)(Wm + (size_t)(k0 + r) * D_FEAT + bn + c4);
            Bs[r][c4 + 0] = f2tf32(v.x);
            Bs[r][c4 + 1] = f2tf32(v.y);
            Bs[r][c4 + 2] = f2tf32(v.z);
            Bs[r][c4 + 3] = f2tf32(v.w);
        }
        __syncthreads();

#pragma unroll
        for (int ks = 0; ks < GBK / 8; ks++) {
            int kk = ks * 8;
            unsigned int a[2][4];
#pragma unroll
            for (int i = 0; i < 2; i++) {
                int mrow = wm * 32 + i * 16;
                a[i][0] = As[kk + q][mrow + g];
                a[i][1] = As[kk + q][mrow + g + 8];
                a[i][2] = As[kk + q + 4][mrow + g];
                a[i][3] = As[kk + q + 4][mrow + g + 8];
            }
            unsigned int b[8][2];
#pragma unroll
            for (int j = 0; j < 8; j++) {
                int ncol = wn * 64 + j * 8 + g;
                b[j][0] = Bs[kk + q][ncol];
                b[j][1] = Bs[kk + q + 4][ncol];
            }
#pragma unroll
            for (int i = 0; i < 2; i++)
#pragma unroll
                for (int j = 0; j < 8; j++) {
                    asm volatile(
                        "mma.sync.aligned.m16n8k8.row.col.f32.tf32.tf32.f32 "
                        "{%0,%1,%2,%3}, {%4,%5,%6,%7}, {%8,%9}, {%0,%1,%2,%3};"
                        : "+f"(c[i][j][0]), "+f"(c[i][j][1]),
                          "+f"(c[i][j][2]), "+f"(c[i][j][3])
                        : "r"(a[i][0]), "r"(a[i][1]), "r"(a[i][2]), "r"(a[i][3]),
                          "r"(b[j][0]), "r"(b[j][1]));
                }
        }
        __syncthreads();
    }

    // Epilogue: v = c*rs_in[row] + b[col]; relu; threefry dropout; store float2
#pragma unroll
    for (int i = 0; i < 2; i++) {
#pragma unroll
        for (int h = 0; h < 2; h++) {
            int row = bm + wm * 32 + i * 16 + h * 8 + g;
            if (row >= M) continue;
            float rs = g_rs_in[row];
#pragma unroll
            for (int j = 0; j < 8; j++) {
                int col = bn + wn * 64 + j * 8 + 2 * q;
                float2 bb = *(const float2*)(bvec + col);
                float v0 = c[i][j][h * 2 + 0] * rs + bb.x;
                float v1 = c[i][j][h * 2 + 1] * rs + bb.y;
                v0 = fmaxf(v0, 0.0f);
                v1 = fmaxf(v1, 0.0f);
                unsigned int flat = (unsigned int)row * D_FEAT + col;
                v0 = dropout_apply(v0, flat);
                v1 = dropout_apply(v1, flat + 1u);
                *(float2*)(out + flat) = make_float2(v0, v1);
            }
        }
    }
}

// ---------------------------------------------------------------------------
// Launch (sequential; streams proved worthless — all kernels fill the chip)
// ---------------------------------------------------------------------------
extern "C" void kernel_launch(void* const* d_in, const int* in_sizes, int n_in,
                              void* d_out, int out_size) {
    const float* feat = (const float*)d_in[0];
    const float* Wm   = (const float*)d_in[1];
    const float* bvec = (const float*)d_in[2];
    const int*   src  = (const int*)d_in[3];
    const int*   dst  = (const int*)d_in[4];
    float* out = (float*)d_out;

    int M  = in_sizes[0] / D_FEAT;   // 50000
    int nE = in_sizes[3];            // 400000

    k_zero_agg<<<(N_TOTAL / 4 + 255) / 256, 256>>>();
    k_zero_deg<<<(N_NODES + 255) / 256, 256>>>();
    k_degrees<<<(nE + 255) / 256, 256>>>(src, dst, nE);
    k_rsqrt<<<(M + 255) / 256, 256>>>(M);
    k_scatter<<<(nE + 7) / 8, 256>>>(feat, src, dst, nE);

    dim3 grid((M + GBM - 1) / GBM, D_FEAT / GBN);
    k_gemm_epilogue<<<grid, 256>>>(Wm, bvec, out, M);
}